// round 6
// baseline (speedup 1.0000x reference)
#include <cuda_runtime.h>
#include <cstdint>

#define ACT_F (4.0f/3.0f)

// ---- layer-1 streams: 64 slots (warp 0..7 x c8 0..7); u32 byte-offset entries
#define SLOT_U32 1088
#define SLOT_LMAX 66
#define DUMMY_ENT 33792u     // (8448 floats)*4 -> zeroed pad slot in xT pos region
#define NEG_OFF_B 33920u     // 8480 floats * 4 -> neg region byte offset

__device__ unsigned g_sbits[5];
__device__ __align__(16) unsigned g_stream[64 * SLOT_U32];
__device__ int g_T1[64];
__device__ __align__(16) unsigned short g_pool2[4096];
__device__ __align__(16) int g_bnd2[324];

// ---------------- prep 1: per-matrix max|w| (1 CTA per matrix, direct write) ----
__global__ void k_scales(const float* W1a, const float* W1b, const float* W2,
                         const float* W3, const float* W4) {
  __shared__ float red[32];
  const float* ptrs[5] = {W1a, W1b, W2, W3, W4};
  const int ns[5] = {131072, 131072, 65536, 8192, 8192};
  int m = blockIdx.x;
  int n4 = ns[m] >> 2;
  const float4* p = (const float4*)ptrs[m];
  float mx = 0.f;
  for (int i = threadIdx.x; i < n4; i += 1024) {
    float4 v = p[i];
    mx = fmaxf(mx, fmaxf(fmaxf(fabsf(v.x), fabsf(v.y)), fmaxf(fabsf(v.z), fabsf(v.w))));
  }
  for (int o = 16; o; o >>= 1) mx = fmaxf(mx, __shfl_xor_sync(0xffffffffu, mx, o));
  if ((threadIdx.x & 31) == 0) red[threadIdx.x >> 5] = mx;
  __syncthreads();
  if (threadIdx.x < 32) {
    mx = red[threadIdx.x];
    for (int o = 16; o; o >>= 1) mx = fmaxf(mx, __shfl_xor_sync(0xffffffffu, mx, o));
    if (threadIdx.x == 0) g_sbits[m] = __float_as_uint(mx);
  }
}

// ---------------- prep 2: layer-1 interleaved streams (u32 entries) ----------------
__global__ void k_build1(const float* W1a, const float* W1b) {
  int wl = threadIdx.x >> 5, lane = threadIdx.x & 31;
  int gw = blockIdx.x * 4 + wl;
  int w = gw >> 3, c8 = gw & 7;
  int mat = c8 >> 2, cl = c8 & 3;
  const float* W = mat ? W1b : W1a;
  float s = __uint_as_float(g_sbits[mat]);
  unsigned* slot = g_stream + gw * SLOT_U32;
  int lens[16];
  int maxlen = 0;
#pragma unroll 1
  for (int j0 = 0; j0 < 16; ++j0) {
    const float* wr = W + (w * 16 + j0) * 1024 + cl * 256;
    int p = 0;
    for (int t = 0; t < 8; ++t) {
      int col = t * 32 + lane;
      float q = rintf(wr[col] / s);
      bool nz = (q != 0.f);
      unsigned mk = __ballot_sync(0xffffffffu, nz);
      if (nz) {
        int pos = p + __popc(mk & ((1u << lane) - 1u));
        if (pos < SLOT_LMAX)
          slot[pos * 16 + j0] =
              (unsigned)(col * 33) * 4u + (q < 0.f ? NEG_OFF_B : 0u);
      }
      p += __popc(mk);
    }
    if (p > SLOT_LMAX) p = SLOT_LMAX;
    lens[j0] = p;
    maxlen = maxlen > p ? maxlen : p;
  }
  int T = maxlen;
#pragma unroll 1
  for (int j0 = 0; j0 < 16; ++j0)
    for (int p = lens[j0] + lane; p < T; p += 32)
      slot[p * 16 + j0] = DUMMY_ENT;
  if (lane == 0) g_T1[gw] = T;
}

// ---------------- prep 3: layers 2-4 CSR in ONE kernel (count/scan/fill) ----------
__device__ __forceinline__ void decode234(int gw, const float* W2, const float* W3,
                                          const float* W4, const float*& W,
                                          int& row, int& len, int& m) {
  if (gw < 128)      { m = 2; row = gw;       len = 512; W = W2; }
  else if (gw < 192) { m = 3; row = gw - 128; len = 128; W = W3; }
  else               { m = 4; row = gw - 192; len = 64;  W = W4; }
}

__global__ void k_build234(const float* W2, const float* W3, const float* W4) {
  __shared__ int cnt[320];
  __shared__ int offs[321];
  int tid = threadIdx.x, w = tid >> 5, lane = tid & 31;
  for (int r = w; r < 320; r += 32) {
    const float* W; int row, len, m;
    decode234(r, W2, W3, W4, W, row, len, m);
    float s = __uint_as_float(g_sbits[m]);
    const float* wr = W + row * len;
    int c = 0;
    for (int t = 0; t < len / 32; ++t) {
      float q = rintf(wr[t * 32 + lane] / s);
      c += __popc(__ballot_sync(0xffffffffu, q != 0.f));
    }
    if (lane == 0) cnt[r] = c;
  }
  __syncthreads();
  if (tid == 0) {
    int run = 0; offs[0] = 0;
    for (int i = 0; i < 320; ++i) { run += cnt[i]; offs[i + 1] = run; }
  }
  __syncthreads();
  for (int i = tid; i < 321; i += 1024) g_bnd2[i] = offs[i];
  if (tid < 3) g_bnd2[321 + tid] = 0;
  for (int r = w; r < 320; r += 32) {
    const float* W; int row, len, m;
    decode234(r, W2, W3, W4, W, row, len, m);
    float s = __uint_as_float(g_sbits[m]);
    const float* wr = W + row * len;
    int pos = offs[r];
    for (int t = 0; t < len / 32; ++t) {
      int idx = t * 32 + lane;
      float q = rintf(wr[idx] / s);
      bool nz = (q != 0.f);
      unsigned mk = __ballot_sync(0xffffffffu, nz);
      if (nz) {
        int p = pos + __popc(mk & ((1u << lane) - 1u));
        if (p < 4096)
          g_pool2[p] = (unsigned short)(idx | (q < 0.f ? 0x8000u : 0u));
      }
      pos += __popc(mk);
    }
  }
}

// ---------------- main fused kernel, occupancy 2 ----------------
// smem: xT pos+neg (16960 f32, stride-33 + dummy), hT/h2T/h3T (u8),
// sE2 pool, sBnd, sT1.  Total 100,128 B -> 2 CTAs/SM.
#define XT_OFF   0
#define HT_OFF   67840
#define H2T_OFF  84224
#define H3T_OFF  88320
#define SE2_OFF  90368
#define SBND_OFF 98560
#define ST1_OFF  99872
#define SMEM_BYTES 100128

#define PR4(A, J) do {                                  \
    acc[(J) + 0] += *(const float*)(xb + (A).x);        \
    acc[(J) + 1] += *(const float*)(xb + (A).y);        \
    acc[(J) + 2] += *(const float*)(xb + (A).z);        \
    acc[(J) + 3] += *(const float*)(xb + (A).w);        \
  } while (0)

__global__ void __launch_bounds__(256, 2) k_main(
    const float* __restrict__ x,
    const float* __restrict__ b1a, const float* __restrict__ b1b,
    const float* __restrict__ b2,  const float* __restrict__ b3,
    float* __restrict__ out) {
  extern __shared__ char smraw[];
  float* xT = (float*)(smraw + XT_OFF);
  unsigned char* hT  = (unsigned char*)(smraw + HT_OFF);
  unsigned char* h2T = (unsigned char*)(smraw + H2T_OFF);
  unsigned char* h3T = (unsigned char*)(smraw + H3T_OFF);
  unsigned short* sE2 = (unsigned short*)(smraw + SE2_OFF);
  int* sBnd = (int*)(smraw + SBND_OFF);
  int* sT1  = (int*)(smraw + ST1_OFF);
  float* outT = (float*)hT;   // alias; hT/h2T dead by layer 4

  int tid = threadIdx.x, lane = tid & 31, warp = tid >> 5;
  const float* xblk = x + (size_t)blockIdx.x * 32 * 4096;
  const char* xb = (const char*)xT + lane * 4;

  // smem metadata copies
  {
    const uint4* gp = (const uint4*)g_pool2;
    uint4* sp = (uint4*)sE2;
    for (int i = tid; i < 512; i += 256) sp[i] = gp[i];
    const uint4* gb = (const uint4*)g_bnd2;
    uint4* sb = (uint4*)sBnd;
    for (int i = tid; i < 81; i += 256) sb[i] = gb[i];
    const uint4* gt = (const uint4*)g_T1;
    uint4* st = (uint4*)sT1;
    for (int i = tid; i < 16; i += 256) st[i] = gt[i];
  }

  float v[32];
  // prologue: chunk 0 -> regs -> xT (pos + neg)
#pragma unroll
  for (int it = 0; it < 32; ++it)
    v[it] = __ldg(xblk + (warp * 4 + (it >> 3)) * 4096 + (it & 7) * 32 + lane);
#pragma unroll
  for (int it = 0; it < 32; ++it) {
    int idx = ((it & 7) * 32 + lane) * 33 + (warp * 4 + (it >> 3));
    float val = v[it];
    xT[idx] = val;
    xT[idx + 8480] = __uint_as_float(__float_as_uint(val) ^ 0x80000000u);
  }
  if (tid < 32) xT[8448 + tid] = 0.f;   // dummy slot (pos region)
  __syncthreads();

  float acc[16];
#pragma unroll 1
  for (int c = 0; c < 16; ++c) {
    if (c < 15) {
      const float* xc = xblk + (c + 1) * 256;
#pragma unroll
      for (int it = 0; it < 32; ++it)
        v[it] = __ldg(xc + (warp * 4 + (it >> 3)) * 4096 + (it & 7) * 32 + lane);
    }
    if ((c & 3) == 0) {
#pragma unroll
      for (int j = 0; j < 16; ++j) acc[j] = 0.f;
    }
    {
      int slot = warp * 8 + (c & 7);
      const uint4* sp = (const uint4*)(g_stream + slot * SLOT_U32);
      int T = sT1[slot];
      uint4 a0 = sp[0], a1 = sp[1], a2 = sp[2], a3 = sp[3];
#pragma unroll 2
      for (int t = 0; t < T; ++t) {
        uint4 n0 = sp[4 * t + 4], n1 = sp[4 * t + 5];
        uint4 n2 = sp[4 * t + 6], n3 = sp[4 * t + 7];
        PR4(a0, 0); PR4(a1, 4); PR4(a2, 8); PR4(a3, 12);
        a0 = n0; a1 = n1; a2 = n2; a3 = n3;
      }
    }
    if ((c & 3) == 3) {                 // end of quarter: bias + quant_relu
      int br = c >> 2;
      const float* bb = (br & 1) ? b1b : b1a;
      float s = __uint_as_float(g_sbits[br & 1]);
#pragma unroll
      for (int j0 = 0; j0 < 16; ++j0) {
        int j = warp * 16 + j0;
        float z = s * acc[j0] + __ldg(bb + j);
        float n = fminf(fmaxf(rintf(z / ACT_F), 0.f), 3.f);
        hT[(br * 128 + j) * 32 + lane] = (unsigned char)n;
      }
    }
    __syncthreads();                    // all gathers done reading xT
    if (c < 15) {
#pragma unroll
      for (int it = 0; it < 32; ++it) {
        int idx = ((it & 7) * 32 + lane) * 33 + (warp * 4 + (it >> 3));
        float val = v[it];
        xT[idx] = val;
        xT[idx + 8480] = __uint_as_float(__float_as_uint(val) ^ 0x80000000u);
      }
      __syncthreads();                  // new chunk visible
    }
  }

  // layer 2: 512 -> 128
  {
    float s2 = __uint_as_float(g_sbits[2]);
#pragma unroll
    for (int j0 = 0; j0 < 16; ++j0) {
      int j = warp * 16 + j0;
      int k = sBnd[j], k1 = sBnd[j + 1];
      int m0 = 0, m1 = 0;
      for (; k + 2 <= k1; k += 2) {
        unsigned e0 = sE2[k], e1 = sE2[k + 1];
        int v0 = hT[(e0 & 511u) * 32u + lane];
        int v1 = hT[(e1 & 511u) * 32u + lane];
        m0 += (e0 & 0x8000u) ? -v0 : v0;
        m1 += (e1 & 0x8000u) ? -v1 : v1;
      }
      if (k < k1) {
        unsigned e0 = sE2[k];
        int v0 = hT[(e0 & 511u) * 32u + lane];
        m0 += (e0 & 0x8000u) ? -v0 : v0;
      }
      float z = s2 * (ACT_F * (float)(m0 + m1)) + __ldg(b2 + j);
      float n = fminf(fmaxf(rintf(z / ACT_F), 0.f), 3.f);
      h2T[j * 32 + lane] = (unsigned char)n;
    }
  }
  __syncthreads();
  // layer 3: 128 -> 64
  {
    float s3 = __uint_as_float(g_sbits[3]);
#pragma unroll
    for (int j0 = 0; j0 < 8; ++j0) {
      int j = warp * 8 + j0;
      int k = sBnd[128 + j], k1 = sBnd[128 + j + 1];
      int m = 0;
      for (; k < k1; ++k) {
        unsigned e = sE2[k];
        int vv = h2T[(e & 127u) * 32u + lane];
        m += (e & 0x8000u) ? -vv : vv;
      }
      float z = s3 * (ACT_F * (float)m) + __ldg(b3 + j);
      float n = fminf(fmaxf(rintf(z / ACT_F), 0.f), 3.f);
      h3T[j * 32 + lane] = (unsigned char)n;
    }
  }
  __syncthreads();
  // layer 4: 64 -> 128 (no bias, no quant)
  {
    float s4 = __uint_as_float(g_sbits[4]);
#pragma unroll
    for (int j0 = 0; j0 < 16; ++j0) {
      int j = warp * 16 + j0;
      int k = sBnd[192 + j], k1 = sBnd[192 + j + 1];
      int m = 0;
      for (; k < k1; ++k) {
        unsigned e = sE2[k];
        int vv = h3T[(e & 63u) * 32u + lane];
        m += (e & 0x8000u) ? -vv : vv;
      }
      outT[j * 33 + lane] = s4 * (ACT_F * (float)m);
    }
  }
  __syncthreads();
  float* og = out + (size_t)blockIdx.x * 32 * 128;
#pragma unroll
  for (int p = 0; p < 16; ++p) {
    int lin = tid + 256 * p;
    int row = lin >> 7, col = lin & 127;
    og[row * 128 + col] = outT[col * 33 + row];
  }
}

extern "C" void kernel_launch(void* const* d_in, const int* in_sizes, int n_in,
                              void* d_out, int out_size) {
  const float* x   = (const float*)d_in[0];
  const float* W1a = (const float*)d_in[1];
  const float* b1a = (const float*)d_in[2];
  const float* W1b = (const float*)d_in[3];
  const float* b1b = (const float*)d_in[4];
  const float* W2  = (const float*)d_in[5];
  const float* b2  = (const float*)d_in[6];
  const float* W3  = (const float*)d_in[7];
  const float* b3  = (const float*)d_in[8];
  const float* W4  = (const float*)d_in[9];
  float* out = (float*)d_out;

  cudaFuncSetAttribute(k_main, cudaFuncAttributeMaxDynamicSharedMemorySize,
                       SMEM_BYTES);
  k_scales<<<5, 1024>>>(W1a, W1b, W2, W3, W4);
  k_build1<<<16, 128>>>(W1a, W1b);
  k_build234<<<1, 1024>>>(W2, W3, W4);
  k_main<<<1024, 256, SMEM_BYTES>>>(x, b1a, b1b, b2, b3, out);
}